// round 11
// baseline (speedup 1.0000x reference)
#include <cuda_runtime.h>

#define BATCH   256
#define TLEN    16384
#define CHUNKS  8
#define CHUNK_T (TLEN / CHUNKS)      // 2048 float2 per chunk
#define THREADS 256
#define PERTHR  8                    // float2 elems per thread
#define NBLK    (BATCH * CHUNKS)     // 2048

__device__ float2 g_chunksums[NBLK];
__device__ float4 g_partials[NBLK];

__constant__ float c_DT    = 0.01f;
__constant__ float c_LCLIP = -4.605170185988091f;  // ln(0.01)
__constant__ float c_EPS   = 1e-6f;

// ---------------- Kernel 1: per-chunk sums of vel_pred ----------------
__global__ __launch_bounds__(THREADS) void k_chunksum(const float* __restrict__ vel) {
    int blk = blockIdx.x;
    int b = blk / CHUNKS, c = blk % CHUNKS;
    int tid = threadIdx.x;
    const float4* vp4 = (const float4*)vel;
    size_t base4 = (((size_t)b * TLEN + (size_t)c * CHUNK_T) >> 1) + (size_t)tid * (PERTHR / 2);
    float sx = 0.f, sy = 0.f;
#pragma unroll
    for (int k = 0; k < PERTHR / 2; k++) {
        float4 a = vp4[base4 + k];
        sx += a.x + a.z;
        sy += a.y + a.w;
    }
#pragma unroll
    for (int o = 16; o; o >>= 1) {
        sx += __shfl_down_sync(0xffffffffu, sx, o);
        sy += __shfl_down_sync(0xffffffffu, sy, o);
    }
    __shared__ float2 ws[THREADS / 32];
    if ((tid & 31) == 0) ws[tid >> 5] = make_float2(sx, sy);
    __syncthreads();
    if (tid == 0) {
        float2 t = ws[0];
#pragma unroll
        for (int i = 1; i < THREADS / 32; i++) { t.x += ws[i].x; t.y += ws[i].y; }
        g_chunksums[blk] = t;
    }
}

// ---------------- Kernel 2: fused scan + all loss terms ----------------
__global__ __launch_bounds__(THREADS) void k_main(const float* __restrict__ vel,
                                                  const float* __restrict__ cov,
                                                  const float* __restrict__ vgt,
                                                  const float* __restrict__ pgt) {
    int blk = blockIdx.x;
    int b = blk / CHUNKS, c = blk % CHUNKS;
    int tid = threadIdx.x;

    size_t rowbase2 = (size_t)b * TLEN;                                 // float2 index of row start
    size_t base4 = ((rowbase2 + (size_t)c * CHUNK_T) >> 1) + (size_t)tid * (PERTHR / 2);

    const float4* vp4 = (const float4*)vel;

    // Load 8 float2 of vel_pred
    float2 v[PERTHR];
#pragma unroll
    for (int k = 0; k < PERTHR / 2; k++) {
        float4 a = vp4[base4 + k];
        v[2 * k]     = make_float2(a.x, a.y);
        v[2 * k + 1] = make_float2(a.z, a.w);
    }

    // Thread-local exclusive prefixes
    float2 pre[PERTHR];
    float2 run = make_float2(0.f, 0.f);
#pragma unroll
    for (int j = 0; j < PERTHR; j++) {
        pre[j] = run;
        run.x += v[j].x;
        run.y += v[j].y;
    }

    // Block inclusive scan of thread totals
    float2 incl = run;
    int lane = tid & 31, warp = tid >> 5;
#pragma unroll
    for (int o = 1; o < 32; o <<= 1) {
        float px = __shfl_up_sync(0xffffffffu, incl.x, o);
        float py = __shfl_up_sync(0xffffffffu, incl.y, o);
        if (lane >= o) { incl.x += px; incl.y += py; }
    }
    __shared__ float2 ws[THREADS / 32];
    if (lane == 31) ws[warp] = incl;
    __syncthreads();
    float2 woff = make_float2(0.f, 0.f);
#pragma unroll
    for (int i = 0; i < THREADS / 32; i++) {
        if (i < warp) { woff.x += ws[i].x; woff.y += ws[i].y; }
    }
    // exclusive offset of this thread inside the chunk
    float2 off = make_float2(woff.x + incl.x - run.x, woff.y + incl.y - run.y);

    // carry-in: sum of previous chunk sums of this row
    float2 carry = make_float2(0.f, 0.f);
#pragma unroll
    for (int i = 0; i < CHUNKS; i++) {
        if (i < c) {
            float2 s = g_chunksums[b * CHUNKS + i];
            carry.x += s.x; carry.y += s.y;
        }
    }
    float2 basep = make_float2(carry.x + off.x, carry.y + off.y);

    float2 v0 = ((const float2*)vel)[rowbase2];   // vel_pred[b, 0, :]

    const float4* pg4 = (const float4*)pgt;
    const float4* vg4 = (const float4*)vgt;
    const float4* cv4 = (const float4*)cov;

    float sp = 0.f, se = 0.f, sm = 0.f, sr = 0.f;

#pragma unroll
    for (int k = 0; k < PERTHR / 2; k++) {
        float4 pg = pg4[base4 + k];
        float4 vg = vg4[base4 + k];
        float4 cc = cv4[base4 + k];
#pragma unroll
        for (int h = 0; h < 2; h++) {
            int j = 2 * k + h;
            float pgx = h ? pg.z : pg.x, pgy = h ? pg.w : pg.y;
            float vgx = h ? vg.z : vg.x, vgy = h ? vg.w : vg.y;
            float c0  = h ? cc.z : cc.x, c1  = h ? cc.w : cc.y;

            // position term
            float ex = basep.x + pre[j].x;
            float ey = basep.y + pre[j].y;
            float px = c_DT * (v0.x + ex);
            float py = c_DT * (v0.y + ey);
            float dpx = px - pgx, dpy = py - pgy;
            sp += dpx * dpx + dpy * dpy;

            // velocity error term
            float evx = v[j].x - vgx, evy = v[j].y - vgy;
            se += evx * evx + evy * evy;

            // NLL term: inv_sigma = min(exp(-c), 100)
            float is0 = fminf(__expf(-c0), 100.0f);
            float is1 = fminf(__expf(-c1), 100.0f);
            sr += is0 + is1;
            float mah = is0 * evx * evx + is1 * evy * evy;
            float z = c_EPS * is0 * is1;                       // <= 1e-2
            float ld = fmaxf(c0, c_LCLIP) + fmaxf(c1, c_LCLIP) + z * (1.0f - 0.5f * z);
            sm += mah + ld;
        }
    }

    // block reduce the 4 accumulators
#pragma unroll
    for (int o = 16; o; o >>= 1) {
        sp += __shfl_down_sync(0xffffffffu, sp, o);
        se += __shfl_down_sync(0xffffffffu, se, o);
        sm += __shfl_down_sync(0xffffffffu, sm, o);
        sr += __shfl_down_sync(0xffffffffu, sr, o);
    }
    __shared__ float4 rs[THREADS / 32];
    if (lane == 0) rs[warp] = make_float4(sp, se, sm, sr);
    __syncthreads();
    if (tid == 0) {
        float4 t = rs[0];
#pragma unroll
        for (int i = 1; i < THREADS / 32; i++) {
            t.x += rs[i].x; t.y += rs[i].y; t.z += rs[i].z; t.w += rs[i].w;
        }
        g_partials[blk] = t;
    }
}

// ---------------- Kernel 3: deterministic finalize ----------------
__global__ __launch_bounds__(THREADS) void k_final(const float* __restrict__ ldv_p,
                                                   const float* __restrict__ ldc_p,
                                                   float* __restrict__ out) {
    int tid = threadIdx.x;
    double sp = 0, se = 0, sm = 0, sr = 0;
    for (int i = tid; i < NBLK; i += THREADS) {
        float4 p = g_partials[i];
        sp += (double)p.x; se += (double)p.y; sm += (double)p.z; sr += (double)p.w;
    }
    __shared__ double sh[4][THREADS];
    sh[0][tid] = sp; sh[1][tid] = se; sh[2][tid] = sm; sh[3][tid] = sr;
    __syncthreads();
    for (int s = THREADS / 2; s > 0; s >>= 1) {
        if (tid < s) {
            sh[0][tid] += sh[0][tid + s];
            sh[1][tid] += sh[1][tid + s];
            sh[2][tid] += sh[2][tid + s];
            sh[3][tid] += sh[3][tid + s];
        }
        __syncthreads();
    }
    if (tid == 0) {
        double N2 = (double)BATCH * TLEN * 2.0;
        double N1 = (double)BATCH * TLEN;
        double lv = sh[0][0] / N2 + sh[1][0] / N2;
        double lc = 0.5 * sh[2][0] / N1;
        double reg = sh[3][0] / N1;
        double ldv = (double)ldv_p[0];
        double ldc = (double)ldc_p[0];
        double dv = exp(ldv), dc = exp(ldc);
        double total = lv / (2.0 * dv * dv) + lc / (2.0 * dc * dc) + ldv + ldc + 0.01 * reg;
        out[0] = (float)total;
    }
}

extern "C" void kernel_launch(void* const* d_in, const int* in_sizes, int n_in,
                              void* d_out, int out_size) {
    const float* vel = (const float*)d_in[0];
    const float* cov = (const float*)d_in[1];
    const float* vgt = (const float*)d_in[2];
    const float* pgt = (const float*)d_in[3];
    const float* ldv = (const float*)d_in[4];
    const float* ldc = (const float*)d_in[5];
    float* out = (float*)d_out;

    k_chunksum<<<NBLK, THREADS>>>(vel);
    k_main<<<NBLK, THREADS>>>(vel, cov, vgt, pgt);
    k_final<<<1, THREADS>>>(ldv, ldc, out);
}

// round 13
// speedup vs baseline: 1.1856x; 1.1856x over previous
#include <cuda_runtime.h>

#define BATCH   256
#define TLEN    16384
#define CHUNKS  4
#define CHUNK_T (TLEN / CHUNKS)      // 4096 float2 positions per chunk
#define THREADS 256
#define NWARP   (THREADS / 32)       // 8
#define ROUNDS  8                    // (CHUNK_T/2 float4) / THREADS = 2048/256
#define NBLK    (BATCH * CHUNKS)     // 1024

__device__ float2 g_chunksums[NBLK];
__device__ float4 g_partials[NBLK];

__constant__ float c_DT    = 0.01f;
__constant__ float c_LCLIP = -4.605170185988091f;  // ln(0.01)
__constant__ float c_EPS   = 1e-6f;

// ---------------- Kernel 1: per-chunk sums of vel_pred (coalesced) ----------------
__global__ __launch_bounds__(THREADS) void k_chunksum(const float* __restrict__ vel) {
    int blk = blockIdx.x;
    int tid = threadIdx.x;
    const float4* vp4 = (const float4*)vel;
    size_t cbase4 = (size_t)blk * (CHUNK_T / 2);   // 2048 float4 per chunk

    float sx = 0.f, sy = 0.f;
#pragma unroll
    for (int r = 0; r < ROUNDS; r++) {
        float4 a = vp4[cbase4 + r * THREADS + tid];   // warp-coalesced
        sx += a.x + a.z;
        sy += a.y + a.w;
    }
#pragma unroll
    for (int o = 16; o; o >>= 1) {
        sx += __shfl_down_sync(0xffffffffu, sx, o);
        sy += __shfl_down_sync(0xffffffffu, sy, o);
    }
    __shared__ float2 ws[NWARP];
    if ((tid & 31) == 0) ws[tid >> 5] = make_float2(sx, sy);
    __syncthreads();
    if (tid == 0) {
        float2 t = ws[0];
#pragma unroll
        for (int i = 1; i < NWARP; i++) { t.x += ws[i].x; t.y += ws[i].y; }
        g_chunksums[blk] = t;
    }
}

// ---------------- Kernel 2: fused coalesced scan + all loss terms ----------------
__global__ __launch_bounds__(THREADS) void k_main(const float* __restrict__ vel,
                                                  const float* __restrict__ cov,
                                                  const float* __restrict__ vgt,
                                                  const float* __restrict__ pgt) {
    int blk = blockIdx.x;
    int b = blk >> 2, c = blk & 3;
    int tid = threadIdx.x, lane = tid & 31, warp = tid >> 5;

    size_t cbase4 = (size_t)blk * (CHUNK_T / 2);
    const float4* vp4 = (const float4*)vel;

    __shared__ float2 ws[ROUNDS][NWARP];

    // Phase A: per-round warp scans of vel sums (coalesced loads)
    float2 excl[ROUNDS];
#pragma unroll
    for (int r = 0; r < ROUNDS; r++) {
        float4 a = vp4[cbase4 + r * THREADS + tid];
        float sx = a.x + a.z, sy = a.y + a.w;
        float ix = sx, iy = sy;
#pragma unroll
        for (int o = 1; o < 32; o <<= 1) {
            float px = __shfl_up_sync(0xffffffffu, ix, o);
            float py = __shfl_up_sync(0xffffffffu, iy, o);
            if (lane >= o) { ix += px; iy += py; }
        }
        excl[r] = make_float2(ix - sx, iy - sy);   // lane-exclusive within (round, warp)
        if (lane == 31) ws[r][warp] = make_float2(ix, iy);  // warp total for round r
    }
    __syncthreads();

    // Carry from previous chunks of this row (fixed order -> deterministic)
    float2 carry = make_float2(0.f, 0.f);
    for (int i = 0; i < c; i++) {
        float2 s = g_chunksums[(b << 2) + i];
        carry.x += s.x; carry.y += s.y;
    }

    // Per-round exclusive base for this thread:
    // P[r] = carry + sum(rounds < r) + sum(warps < mine in round r) + lane-exclusive
    float2 P[ROUNDS];
    float2 A = carry;
#pragma unroll
    for (int r = 0; r < ROUNDS; r++) {
        float wx = 0.f, wy = 0.f, rtx = 0.f, rty = 0.f;
#pragma unroll
        for (int w = 0; w < NWARP; w++) {
            float2 t = ws[r][w];
            if (w < warp) { wx += t.x; wy += t.y; }
            rtx += t.x; rty += t.y;
        }
        P[r] = make_float2(A.x + wx + excl[r].x, A.y + wy + excl[r].y);
        A.x += rtx; A.y += rty;
    }

    float2 v0row = ((const float2*)vel)[(size_t)b * TLEN];   // vel_pred[b, 0, :]

    const float4* pg4 = (const float4*)pgt;
    const float4* vg4 = (const float4*)vgt;
    const float4* cv4 = (const float4*)cov;

    float sp = 0.f, se = 0.f, sm = 0.f, sr = 0.f;

    // Phase B: streaming loss pass (all loads warp-coalesced; vel reload hits L1/L2)
#pragma unroll
    for (int r = 0; r < ROUNDS; r++) {
        size_t idx = cbase4 + r * THREADS + tid;
        float4 a  = vp4[idx];
        float4 pg = pg4[idx];
        float4 vg = vg4[idx];
        float4 cc = cv4[idx];

#pragma unroll
        for (int h = 0; h < 2; h++) {
            float vx  = h ? a.z  : a.x,  vy  = h ? a.w  : a.y;
            float pgx = h ? pg.z : pg.x, pgy = h ? pg.w : pg.y;
            float vgx = h ? vg.z : vg.x, vgy = h ? vg.w : vg.y;
            float c0  = h ? cc.z : cc.x, c1  = h ? cc.w : cc.y;

            float ex = h ? (P[r].x + a.x) : P[r].x;   // element 1 adds element 0's vel
            float ey = h ? (P[r].y + a.y) : P[r].y;

            // position term
            float px = c_DT * (v0row.x + ex);
            float py = c_DT * (v0row.y + ey);
            float dpx = px - pgx, dpy = py - pgy;
            sp += dpx * dpx + dpy * dpy;

            // velocity error term
            float evx = vx - vgx, evy = vy - vgy;
            se += evx * evx + evy * evy;

            // NLL: inv_sigma = min(exp(-c), 100)
            float is0 = fminf(__expf(-c0), 100.0f);
            float is1 = fminf(__expf(-c1), 100.0f);
            sr += is0 + is1;
            float mah = is0 * evx * evx + is1 * evy * evy;
            float z = c_EPS * is0 * is1;   // <= 1e-2
            float ld = fmaxf(c0, c_LCLIP) + fmaxf(c1, c_LCLIP) + z * (1.0f - 0.5f * z);
            sm += mah + ld;
        }
    }

    // block reduce the 4 accumulators
#pragma unroll
    for (int o = 16; o; o >>= 1) {
        sp += __shfl_down_sync(0xffffffffu, sp, o);
        se += __shfl_down_sync(0xffffffffu, se, o);
        sm += __shfl_down_sync(0xffffffffu, sm, o);
        sr += __shfl_down_sync(0xffffffffu, sr, o);
    }
    __shared__ float4 rs[NWARP];
    if (lane == 0) rs[warp] = make_float4(sp, se, sm, sr);
    __syncthreads();
    if (tid == 0) {
        float4 t = rs[0];
#pragma unroll
        for (int i = 1; i < NWARP; i++) {
            t.x += rs[i].x; t.y += rs[i].y; t.z += rs[i].z; t.w += rs[i].w;
        }
        g_partials[blk] = t;
    }
}

// ---------------- Kernel 3: deterministic finalize ----------------
__global__ __launch_bounds__(THREADS) void k_final(const float* __restrict__ ldv_p,
                                                   const float* __restrict__ ldc_p,
                                                   float* __restrict__ out) {
    int tid = threadIdx.x;
    double sp = 0, se = 0, sm = 0, sr = 0;
    for (int i = tid; i < NBLK; i += THREADS) {
        float4 p = g_partials[i];
        sp += (double)p.x; se += (double)p.y; sm += (double)p.z; sr += (double)p.w;
    }
    __shared__ double sh[4][THREADS];
    sh[0][tid] = sp; sh[1][tid] = se; sh[2][tid] = sm; sh[3][tid] = sr;
    __syncthreads();
    for (int s = THREADS / 2; s > 0; s >>= 1) {
        if (tid < s) {
            sh[0][tid] += sh[0][tid + s];
            sh[1][tid] += sh[1][tid + s];
            sh[2][tid] += sh[2][tid + s];
            sh[3][tid] += sh[3][tid + s];
        }
        __syncthreads();
    }
    if (tid == 0) {
        double N2 = (double)BATCH * TLEN * 2.0;
        double N1 = (double)BATCH * TLEN;
        double lv = sh[0][0] / N2 + sh[1][0] / N2;
        double lc = 0.5 * sh[2][0] / N1;
        double reg = sh[3][0] / N1;
        double ldv = (double)ldv_p[0];
        double ldc = (double)ldc_p[0];
        double dv = exp(ldv), dc = exp(ldc);
        double total = lv / (2.0 * dv * dv) + lc / (2.0 * dc * dc) + ldv + ldc + 0.01 * reg;
        out[0] = (float)total;
    }
}

extern "C" void kernel_launch(void* const* d_in, const int* in_sizes, int n_in,
                              void* d_out, int out_size) {
    const float* vel = (const float*)d_in[0];
    const float* cov = (const float*)d_in[1];
    const float* vgt = (const float*)d_in[2];
    const float* pgt = (const float*)d_in[3];
    const float* ldv = (const float*)d_in[4];
    const float* ldc = (const float*)d_in[5];
    float* out = (float*)d_out;

    k_chunksum<<<NBLK, THREADS>>>(vel);
    k_main<<<NBLK, THREADS>>>(vel, cov, vgt, pgt);
    k_final<<<1, THREADS>>>(ldv, ldc, out);
}